// round 3
// baseline (speedup 1.0000x reference)
#include <cuda_runtime.h>
#include <cstdint>

// Problem shape (fixed): B=8, S=4096, E=512, H=8, Dh=64, window=5
#define M_TOT 32768   // B*S
#define N_TOT 512
#define K_TOT 512

#define BM 128
#define BN 128
#define BKK 32
#define NTHREADS 256

// Scratch (device globals: the sanctioned no-alloc workaround)
__device__ float g_V [M_TOT * N_TOT];
__device__ float g_Vc[M_TOT * N_TOT];

__device__ __forceinline__ uint32_t f2tf(float x) {
    uint32_t u;
    asm("cvt.rna.tf32.f32 %0, %1;" : "=r"(u) : "f"(x));
    return u;
}

// C[m,n] = sum_k A[m,k] * B[n,k]   (A: [M,K] row-major, B: [N,K] row-major)
// tf32 mma.sync m16n8k8, fp32 accumulate.
__global__ __launch_bounds__(NTHREADS)
void gemm_tf32_kernel(const float* __restrict__ A,
                      const float* __restrict__ B,
                      float* __restrict__ C)
{
    __shared__ float As[BM][BKK + 4];
    __shared__ float Bs[BKK][BN + 4];

    const int bm   = blockIdx.y * BM;
    const int bn   = blockIdx.x * BN;
    const int tid  = threadIdx.x;
    const int warp = tid >> 5;
    const int lane = tid & 31;
    const int wm   = warp >> 2;   // 0..1  -> 64-row warp stripe
    const int wn   = warp & 3;    // 0..3  -> 32-col warp stripe
    const int lr   = lane >> 2;   // groupID 0..7
    const int lc   = lane & 3;    // threadID-in-group 0..3

    float acc[4][4][4];
    #pragma unroll
    for (int mt = 0; mt < 4; mt++)
        #pragma unroll
        for (int nt = 0; nt < 4; nt++)
            #pragma unroll
            for (int r = 0; r < 4; r++)
                acc[mt][nt][r] = 0.0f;

    for (int k0 = 0; k0 < K_TOT; k0 += BKK) {
        // ---- load A tile: 128 x 32 fp32, tf32-round on the way in ----
        #pragma unroll
        for (int i = 0; i < 4; i++) {
            int idx = tid + i * NTHREADS;      // 0..1023 float4 slots
            int m   = idx >> 3;                // 0..127
            int kq  = (idx & 7) << 2;          // 0,4,...,28
            float4 v = *reinterpret_cast<const float4*>(
                &A[(size_t)(bm + m) * K_TOT + k0 + kq]);
            As[m][kq + 0] = __uint_as_float(f2tf(v.x));
            As[m][kq + 1] = __uint_as_float(f2tf(v.y));
            As[m][kq + 2] = __uint_as_float(f2tf(v.z));
            As[m][kq + 3] = __uint_as_float(f2tf(v.w));
        }
        // ---- load B tile: [N=128] rows x [K=32] -> transposed to Bs[k][n] ----
        #pragma unroll
        for (int i = 0; i < 4; i++) {
            int idx = tid + i * NTHREADS;
            int n   = idx >> 3;
            int kq  = (idx & 7) << 2;
            float4 v = *reinterpret_cast<const float4*>(
                &B[(size_t)(bn + n) * K_TOT + k0 + kq]);
            Bs[kq + 0][n] = __uint_as_float(f2tf(v.x));
            Bs[kq + 1][n] = __uint_as_float(f2tf(v.y));
            Bs[kq + 2][n] = __uint_as_float(f2tf(v.z));
            Bs[kq + 3][n] = __uint_as_float(f2tf(v.w));
        }
        __syncthreads();

        #pragma unroll
        for (int ks = 0; ks < BKK; ks += 8) {
            uint32_t afr[4][4];
            #pragma unroll
            for (int mt = 0; mt < 4; mt++) {
                int mr = wm * 64 + mt * 16;
                afr[mt][0] = __float_as_uint(As[mr + lr    ][ks + lc    ]);
                afr[mt][1] = __float_as_uint(As[mr + 8 + lr][ks + lc    ]);
                afr[mt][2] = __float_as_uint(As[mr + lr    ][ks + 4 + lc]);
                afr[mt][3] = __float_as_uint(As[mr + 8 + lr][ks + 4 + lc]);
            }
            uint32_t bfr[4][2];
            #pragma unroll
            for (int nt = 0; nt < 4; nt++) {
                int nc = wn * 32 + nt * 8 + lr;
                bfr[nt][0] = __float_as_uint(Bs[ks + lc    ][nc]);
                bfr[nt][1] = __float_as_uint(Bs[ks + 4 + lc][nc]);
            }
            #pragma unroll
            for (int mt = 0; mt < 4; mt++)
                #pragma unroll
                for (int nt = 0; nt < 4; nt++) {
                    asm volatile(
                        "mma.sync.aligned.m16n8k8.row.col.f32.tf32.tf32.f32 "
                        "{%0,%1,%2,%3}, {%4,%5,%6,%7}, {%8,%9}, {%0,%1,%2,%3};"
                        : "+f"(acc[mt][nt][0]), "+f"(acc[mt][nt][1]),
                          "+f"(acc[mt][nt][2]), "+f"(acc[mt][nt][3])
                        : "r"(afr[mt][0]), "r"(afr[mt][1]),
                          "r"(afr[mt][2]), "r"(afr[mt][3]),
                          "r"(bfr[nt][0]), "r"(bfr[nt][1]));
                }
        }
        __syncthreads();
    }

    // ---- epilogue: fp32 out ----
    #pragma unroll
    for (int mt = 0; mt < 4; mt++) {
        int m = bm + wm * 64 + mt * 16 + lr;
        #pragma unroll
        for (int nt = 0; nt < 4; nt++) {
            int n = bn + wn * 32 + nt * 8 + lc * 2;
            float2 v0 = make_float2(acc[mt][nt][0], acc[mt][nt][1]);
            float2 v1 = make_float2(acc[mt][nt][2], acc[mt][nt][3]);
            *reinterpret_cast<float2*>(&C[(size_t)m * N_TOT + n])       = v0;
            *reinterpret_cast<float2*>(&C[(size_t)(m + 8) * N_TOT + n]) = v1;
        }
    }
}

// 5-tap Gaussian smoothing along sequence, per-head shift {0,-1,+1,0} x2,
// zero-padded at each batch boundary. One thread = 4 channels (float4).
__global__ void conv_kernel(const float4* __restrict__ V, float4* __restrict__ Vc)
{
    int idx = blockIdx.x * blockDim.x + threadIdx.x;  // 32768*128 total
    int c4  = idx & 127;        // float4 column (512/4)
    int m   = idx >> 7;         // 0..32767 (b*4096 + s)
    int s   = m & 4095;
    int mb0 = m - s;            // batch base row
    int h   = c4 >> 4;          // head = (c4*4)/64
    int hm  = h & 3;
    int shift = (hm == 1) ? -1 : ((hm == 2) ? 1 : 0);

    const float F0 = 0.05399096651318806f;   // c*exp(-2)
    const float F1 = 0.24197072451914337f;   // c*exp(-0.5)
    const float F2 = 0.3989422804014327f;    // c
    const float F[5] = {F0, F1, F2, F1, F0};

    float ax = 0.f, ay = 0.f, az = 0.f, aw = 0.f;
    #pragma unroll
    for (int j = 0; j < 5; j++) {
        int ss = s + shift + j - 2;
        if (ss >= 0 && ss < 4096) {
            float4 v = V[(size_t)(mb0 + ss) * 128 + c4];
            ax += F[j] * v.x;
            ay += F[j] * v.y;
            az += F[j] * v.z;
            aw += F[j] * v.w;
        }
    }
    Vc[idx] = make_float4(ax, ay, az, aw);
}

extern "C" void kernel_launch(void* const* d_in, const int* in_sizes, int n_in,
                              void* d_out, int out_size)
{
    // metadata order: values, keys(unused), queries(unused), input_weights, out_proj_w
    const float* values = (const float*)d_in[0];
    const float* win    = (const float*)d_in[3];
    const float* wout   = (const float*)d_in[4];
    float*       out    = (float*)d_out;

    float *pV = nullptr, *pVc = nullptr;
    cudaGetSymbolAddress((void**)&pV,  g_V);
    cudaGetSymbolAddress((void**)&pVc, g_Vc);

    dim3 grid(N_TOT / BN, M_TOT / BM);  // (4, 256)

    // Pass 1: V = values @ Win^T
    gemm_tf32_kernel<<<grid, NTHREADS>>>(values, win, pV);
    // Pass 2: depthwise Gaussian window per head
    conv_kernel<<<(M_TOT * 128) / 256, 256>>>((const float4*)pV, (float4*)pVc);
    // Pass 3: out = Vc @ Wout^T
    gemm_tf32_kernel<<<grid, NTHREADS>>>(pVc, wout, out);
}